// round 16
// baseline (speedup 1.0000x reference)
#include <cuda_runtime.h>
#include <cuda_fp16.h>
#include <math.h>
#include <stdint.h>

#define BB 2
#define SS 2048
#define HH 16
#define DD 64
#define HID 1024
#define NTOK (BB * SS)
#define LOG2E 1.4426950408889634f
#define QSCALE (0.125f * LOG2E)
#define MASKADD (-64.0f)     // log2-domain; exp2(-64) == 0 in fp16

// -------- scratch (allocation-free __device__ globals) --------
__device__ __half g_x[(size_t)NTOK * HID];               // x, fp16
__device__ __half g_Wkn[(size_t)3 * HID * HID];          // W [k][n], fp16 (no transpose)
__device__ __half g_Qh[(size_t)NTOK * HID];              // [b][h][s][d]
__device__ __half g_Kh[(size_t)NTOK * HID];
__device__ __half g_Vh[(size_t)NTOK * HID];

// ===================== helpers =====================
__device__ __forceinline__ uint32_t smem_u32(const void* p) {
    uint32_t a;
    asm("{ .reg .u64 t; cvta.to.shared.u64 t, %1; cvt.u32.u64 %0, t; }" : "=r"(a) : "l"(p));
    return a;
}
__device__ __forceinline__ uint32_t sw128(uint32_t o) { return o ^ ((o >> 3) & 0x70); }
// swizzle for 256-byte rows: phase = row & 7 (bits 8-10 of offset)
__device__ __forceinline__ uint32_t sw256(uint32_t o) { return o ^ ((o >> 4) & 0x70); }

__device__ __forceinline__ void ldsm4(uint32_t r[4], uint32_t addr) {
    asm volatile("ldmatrix.sync.aligned.m8n8.x4.shared.b16 {%0,%1,%2,%3}, [%4];"
                 : "=r"(r[0]), "=r"(r[1]), "=r"(r[2]), "=r"(r[3]) : "r"(addr));
}
__device__ __forceinline__ void ldsm4t(uint32_t r[4], uint32_t addr) {
    asm volatile("ldmatrix.sync.aligned.m8n8.x4.trans.shared.b16 {%0,%1,%2,%3}, [%4];"
                 : "=r"(r[0]), "=r"(r[1]), "=r"(r[2]), "=r"(r[3]) : "r"(addr));
}
// fp16 MMA, f32 accumulate
__device__ __forceinline__ void mma16816(float c[4], const uint32_t a[4],
                                         uint32_t b0, uint32_t b1) {
    asm volatile(
        "mma.sync.aligned.m16n8k16.row.col.f32.f16.f16.f32 "
        "{%0,%1,%2,%3}, {%4,%5,%6,%7}, {%8,%9}, {%0,%1,%2,%3};"
        : "+f"(c[0]), "+f"(c[1]), "+f"(c[2]), "+f"(c[3])
        : "r"(a[0]), "r"(a[1]), "r"(a[2]), "r"(a[3]), "r"(b0), "r"(b1));
}
// pack RN-fp16 pair: e0 -> low half, e1 -> high half
__device__ __forceinline__ uint32_t packh(float e0, float e1) {
    __half2 h = __floats2half2_rn(e0, e1);
    return *reinterpret_cast<uint32_t*>(&h);
}
// hardware exp2: one MUFU.EX2 (parallel pipe to tensor)
__device__ __forceinline__ float ex2(float x) {
    float y;
    asm("ex2.approx.ftz.f32 %0, %1;" : "=f"(y) : "f"(x));
    return y;
}
__device__ __forceinline__ void cpa16(uint32_t s, const void* g) {
    asm volatile("cp.async.cg.shared.global [%0], [%1], 16;" :: "r"(s), "l"(g));
}
#define CPA_COMMIT() asm volatile("cp.async.commit_group;")
#define CPA_WAIT2()  asm volatile("cp.async.wait_group 2;")
#define CPA_WAIT1()  asm volatile("cp.async.wait_group 1;")
#define CPA_WAIT0()  asm volatile("cp.async.wait_group 0;")

#define ONESF16X2 0x3C003C00u     // half2(1.0, 1.0)

// ===================== prep: pure streaming fp32->fp16 convert =====================
// grid (1024, 1, 7): z<3 -> W slice z (1M floats each), z>=3 -> x quarter z-3.
__global__ void conv_all(const float* __restrict__ x,
                         const float* __restrict__ Wq, const float* __restrict__ Wk,
                         const float* __restrict__ Wv) {
    const int z = blockIdx.z;
    const size_t i = ((size_t)blockIdx.x * 256 + threadIdx.x) * 4;
    if (z < 3) {
        const float* W = (z == 0) ? Wq : (z == 1) ? Wk : Wv;
        float4 v = *(const float4*)(W + i);
        *(uint2*)(g_Wkn + (size_t)z * HID * HID + i) =
            make_uint2(packh(v.x, v.y), packh(v.z, v.w));
    } else {
        size_t off = (size_t)(z - 3) * (HID * HID) + i;
        float4 v = *(const float4*)(x + off);
        *(uint2*)(g_x + off) = make_uint2(packh(v.x, v.y), packh(v.z, v.w));
    }
}

// ===================== QKV GEMM: BM128 x BN128 x BK64, warp tile 32x64 =============
// A tile: 128 m-rows x 128B (sw128). B tile: 64 k-rows x 256B [k][n] (sw256),
// consumed via ldmatrix.trans (same pattern as attention's V path).
// stage: A@0(16K) B@16K(16K) = 32K; 3 stages = 96K.
#define GSTAGE 32768
#define GSMEM  (3 * GSTAGE)      // 98304
#define NCHUNK 16

__global__ __launch_bounds__(256, 2)
void qkv_gemm_mma(const float* __restrict__ bq, const float* __restrict__ bk,
                  const float* __restrict__ bv) {
    extern __shared__ __align__(1024) char sm[];
    const int tid = threadIdx.x, lane = tid & 31, wid = tid >> 5;
    const int wm = wid >> 1, wn = wid & 1;     // 4m x 2n warp grid, 32x64 tiles
    const int z = blockIdx.z;
    const int m0 = blockIdx.y * 128;
    const int n0 = blockIdx.x * 128;

    const __half* Wh = g_Wkn + (size_t)z * HID * HID;
    const float* bias = (z == 0) ? bq : (z == 1) ? bk : bv;
    const uint32_t smb = smem_u32(sm);

    auto issue = [&](int c, int s) {
        const uint32_t sb = smb + s * GSTAGE;
        const int k0 = c * 64;
#pragma unroll
        for (int j = 0; j < 4; j++) {               // A: 128 m-rows x 8 x 16B
            int idx = tid + 256 * j;
            int row = idx >> 3, ch = idx & 7;
            uint32_t so = sw128((uint32_t)(row * 128 + ch * 16));
            cpa16(sb + so, g_x + (size_t)(m0 + row) * HID + k0 + ch * 8);
        }
#pragma unroll
        for (int j = 0; j < 4; j++) {               // B: 64 k-rows x 16 x 16B
            int idx = tid + 256 * j;
            int row = idx >> 4, ch = idx & 15;
            uint32_t so = sw256((uint32_t)(row * 256 + ch * 16));
            cpa16(sb + 16384 + so, Wh + (size_t)(k0 + row) * HID + n0 + ch * 8);
        }
        CPA_COMMIT();
    };

    float acc[2][8][4];
#pragma unroll
    for (int i = 0; i < 2; i++)
#pragma unroll
        for (int j = 0; j < 8; j++)
#pragma unroll
            for (int v = 0; v < 4; v++) acc[i][j][v] = 0.f;

    issue(0, 0); issue(1, 1); issue(2, 2);

    uint32_t offA[4], offB[4];
    {
        const int rA = wm * 32 + (lane & 15);
#pragma unroll
        for (int kk = 0; kk < 4; kk++) {
            const int cA = kk * 32 + (lane >> 4) * 16;
            offA[kk] = sw128((uint32_t)(rA * 128 + cA));
        }
        // B: rows = k (lane&15), col bytes = wn*128 + dg*32 + (lane>>4)*16
        const int rB = lane & 15;
#pragma unroll
        for (int dg = 0; dg < 4; dg++) {
            const int cB = wn * 128 + dg * 32 + (lane >> 4) * 16;
            offB[dg] = 16384 + sw256((uint32_t)(rB * 256 + cB));
        }
    }

    for (int c = 0; c < NCHUNK; c++) {
        const int s = c % 3;
        const uint32_t sb = smb + s * GSTAGE;
        if (c <= NCHUNK - 3) CPA_WAIT2();
        else if (c == NCHUNK - 2) CPA_WAIT1();
        else CPA_WAIT0();
        __syncthreads();

#pragma unroll
        for (int kk = 0; kk < 4; kk++) {
            const uint32_t aA = sb + offA[kk];
            uint32_t ah[2][4];
            ldsm4(ah[0], aA);           ldsm4(ah[1], aA + 2048);
            const uint32_t kb = kk * 4096;      // 16 k-rows x 256B
#pragma unroll
            for (int dg = 0; dg < 4; dg++) {
                uint32_t bt[4];
                ldsm4t(bt, sb + offB[dg] + kb);
#pragma unroll
                for (int mi = 0; mi < 2; mi++) {
                    mma16816(acc[mi][2 * dg],     ah[mi], bt[0], bt[1]);
                    mma16816(acc[mi][2 * dg + 1], ah[mi], bt[2], bt[3]);
                }
            }
        }
        __syncthreads();
        if (c + 3 < NCHUNK) issue(c + 3, (c + 3) % 3);
    }

    __half* outh = (z == 0) ? g_Qh : (z == 1) ? g_Kh : g_Vh;
    const float sc = (z == 0) ? QSCALE : 1.0f;
#pragma unroll
    for (int mi = 0; mi < 2; mi++) {
        int r0 = m0 + wm * 32 + mi * 16 + (lane >> 2);
#pragma unroll
        for (int nj = 0; nj < 8; nj++) {
            int col = n0 + wn * 64 + nj * 8 + 2 * (lane & 3);
            float b0v = __ldg(&bias[col]), b1v = __ldg(&bias[col + 1]);
#pragma unroll
            for (int half_ = 0; half_ < 2; half_++) {
                int r = r0 + half_ * 8;
                float v0 = (acc[mi][nj][half_ * 2 + 0] + b0v) * sc;
                float v1 = (acc[mi][nj][half_ * 2 + 1] + b1v) * sc;
                size_t off = (((size_t)((r >> 11) * HH + (col >> 6)) * SS +
                               (r & (SS - 1))) * DD) + (col & (DD - 1));
                *(uint32_t*)(outh + off) = packh(v0, v1);
            }
        }
    }
}

// ===================== flash attention (unchanged from R14) =====================
#define ASTAGE 32768
#define AADDER (3 * ASTAGE)              // 98304
#define AFLAGS (AADDER + SS * 4)         // 106496
#define ASMEM  (AFLAGS + 128)            // 106624
#define NPAIR 16

__global__ __launch_bounds__(256, 2)
void attn_mma(const int* __restrict__ mask, float* __restrict__ out) {
    extern __shared__ __align__(1024) char sm[];
    const int tid = threadIdx.x, lane = tid & 31, wid = tid >> 5;
    const int q0 = blockIdx.x * 128;
    const int h = blockIdx.y, b = blockIdx.z;
    const size_t hb = (size_t)(b * HH + h) * SS * DD;
    const uint32_t smb = smem_u32(sm);

    // ---- prologue: stage Q, mask adders ----
#pragma unroll
    for (int j = 0; j < 4; j++) {
        int idx = tid + 256 * j;
        int row = idx >> 3, ch = idx & 7;
        uint32_t so = sw128((uint32_t)(row * 128 + ch * 16));
        *(uint4*)(sm + so) = *(const uint4*)(g_Qh + hb + (size_t)(q0 + row) * DD + ch * 8);
    }
#pragma unroll
    for (int j = 0; j < SS / 256; j++) {
        int i = tid + 256 * j;
        ((float*)(sm + AADDER))[i] = mask[b * SS + i] ? 0.f : MASKADD;
    }
    __syncthreads();
    uint32_t qh[4][4];
    {
        int r = wid * 16 + (lane & 15);
#pragma unroll
        for (int kk = 0; kk < 4; kk++) {
            int cB = kk * 32 + (lane >> 4) * 16;
            ldsm4(qh[kk], smb + sw128((uint32_t)(r * 128 + cB)));
        }
    }
    // per-64-key-block "fully unmasked" flags
    if (tid < 32) {
        const float* ad = (const float*)(sm + AADDER) + tid * 64;
        int ok = 1;
#pragma unroll 8
        for (int i = 0; i < 64; i++) ok &= (ad[i] == 0.0f);
        ((int*)(sm + AFLAGS))[tid] = ok;
    }
    __syncthreads();

    auto issue = [&](int p, int s) {       // loads 128 keys (pair p) into stage s
        const uint32_t sb = smb + s * ASTAGE;
        const int c0 = p * 128;
#pragma unroll
        for (int j = 0; j < 4; j++) {
            int idx = tid + 256 * j;
            int row = idx >> 3, ch = idx & 7;
            uint32_t so = sw128((uint32_t)(row * 128 + ch * 16));
            size_t g = hb + (size_t)(c0 + row) * DD + ch * 8;
            cpa16(sb + so,         g_Kh + g);
            cpa16(sb + 16384 + so, g_Vh + g);
        }
        CPA_COMMIT();
    };

    float ctx[8][4];
#pragma unroll
    for (int i = 0; i < 8; i++)
#pragma unroll
        for (int j = 0; j < 4; j++) ctx[i][j] = 0.f;
    float lacc[4] = {0.f, 0.f, 0.f, 0.f};

    issue(0, 0); issue(1, 1); issue(2, 2);

    uint32_t off4[4];
    {
        const int rk = lane & 15;
#pragma unroll
        for (int i = 0; i < 4; i++) {
            const int cB = i * 32 + (lane >> 4) * 16;
            off4[i] = sw128((uint32_t)(rk * 128 + cB));
        }
    }
    const int kcol = 2 * (lane & 3);
    const int* flags = (const int*)(sm + AFLAGS);

    for (int p = 0; p < NPAIR; p++) {
        const int s = p % 3;
        const uint32_t sb = smb + s * ASTAGE;
        if (p <= NPAIR - 3) CPA_WAIT2();
        else if (p == NPAIR - 2) CPA_WAIT1();
        else CPA_WAIT0();
        __syncthreads();

#pragma unroll
        for (int hf = 0; hf < 2; hf++) {
            const int c = 2 * p + hf;
            const uint32_t koff = hf * 8192;

            float sacc[8][4];
#pragma unroll
            for (int i = 0; i < 8; i++)
#pragma unroll
                for (int j = 0; j < 4; j++) sacc[i][j] = 0.f;

#pragma unroll
            for (int kk = 0; kk < 4; kk++) {
                const uint32_t ka = sb + koff + off4[kk];
#pragma unroll
                for (int g = 0; g < 4; g++) {
                    uint32_t kh[4];
                    ldsm4(kh, ka + g * 2048);
                    mma16816(sacc[2 * g],     qh[kk], kh[0], kh[2]);
                    mma16816(sacc[2 * g + 1], qh[kk], kh[1], kh[3]);
                }
            }

            uint32_t ph[4][4];
            if (flags[c]) {
#pragma unroll
                for (int kg = 0; kg < 4; kg++) {
                    const float* s0 = sacc[2 * kg];
                    const float* s1 = sacc[2 * kg + 1];
                    ph[kg][0] = packh(ex2(s0[0]), ex2(s0[1]));
                    ph[kg][1] = packh(ex2(s0[2]), ex2(s0[3]));
                    ph[kg][2] = packh(ex2(s1[0]), ex2(s1[1]));
                    ph[kg][3] = packh(ex2(s1[2]), ex2(s1[3]));
                }
            } else {
                const float* madd = (const float*)(sm + AADDER) + c * 64;
#pragma unroll
                for (int kg = 0; kg < 4; kg++) {
                    const float* s0 = sacc[2 * kg];
                    const float* s1 = sacc[2 * kg + 1];
                    float a0 = madd[kg * 16 + kcol];
                    float a1 = madd[kg * 16 + kcol + 1];
                    float a2 = madd[kg * 16 + 8 + kcol];
                    float a3 = madd[kg * 16 + 8 + kcol + 1];
                    ph[kg][0] = packh(ex2(s0[0] + a0), ex2(s0[1] + a1));
                    ph[kg][1] = packh(ex2(s0[2] + a0), ex2(s0[3] + a1));
                    ph[kg][2] = packh(ex2(s1[0] + a2), ex2(s1[1] + a3));
                    ph[kg][3] = packh(ex2(s1[2] + a2), ex2(s1[3] + a3));
                }
            }

#pragma unroll
            for (int kg = 0; kg < 4; kg++)
                mma16816(lacc, ph[kg], ONESF16X2, ONESF16X2);

#pragma unroll
            for (int dg = 0; dg < 4; dg++) {
                const uint32_t va = sb + 16384 + koff + off4[dg];
#pragma unroll
                for (int kg = 0; kg < 4; kg++) {
                    uint32_t vh[4];
                    ldsm4t(vh, va + kg * 2048);
                    mma16816(ctx[2 * dg],     ph[kg], vh[0], vh[1]);
                    mma16816(ctx[2 * dg + 1], ph[kg], vh[2], vh[3]);
                }
            }
        }
        __syncthreads();
        if (p + 3 < NPAIR) issue(p + 3, (p + 3) % 3);
    }

    const float inv0 = 1.0f / lacc[0], inv1 = 1.0f / lacc[2];
    const int r0 = q0 + wid * 16 + (lane >> 2);
    const int dbase = 2 * (lane & 3);
#pragma unroll
    for (int nj = 0; nj < 8; nj++) {
        int d = nj * 8 + dbase;
        float2 v0 = make_float2(ctx[nj][0] * inv0, ctx[nj][1] * inv0);
        float2 v1 = make_float2(ctx[nj][2] * inv1, ctx[nj][3] * inv1);
        *(float2*)&out[(size_t)(b * SS + r0) * HID + h * DD + d] = v0;
        *(float2*)&out[(size_t)(b * SS + r0 + 8) * HID + h * DD + d] = v1;
    }
}

// ===================== launch =====================
extern "C" void kernel_launch(void* const* d_in, const int* in_sizes, int n_in,
                              void* d_out, int out_size) {
    const float* x    = (const float*)d_in[0];
    const int*   mask = (const int*)d_in[1];
    const float* Wq   = (const float*)d_in[2];
    const float* bq   = (const float*)d_in[3];
    const float* Wk   = (const float*)d_in[4];
    const float* bk   = (const float*)d_in[5];
    const float* Wv   = (const float*)d_in[6];
    const float* bv   = (const float*)d_in[7];
    float* out = (float*)d_out;

    static int attr_done = 0;
    if (!attr_done) {
        cudaFuncSetAttribute(qkv_gemm_mma,
                             cudaFuncAttributeMaxDynamicSharedMemorySize, GSMEM);
        cudaFuncSetAttribute(attn_mma,
                             cudaFuncAttributeMaxDynamicSharedMemorySize, ASMEM);
        attr_done = 1;
    }

    dim3 pgrid(1024, 1, 7);
    conv_all<<<pgrid, 256>>>(x, Wq, Wk, Wv);

    dim3 ggrid(HID / 128, NTOK / 128, 3);
    qkv_gemm_mma<<<ggrid, 256, GSMEM>>>(bq, bk, bv);

    dim3 agrid(SS / 128, HH, BB);
    attn_mma<<<agrid, 256, ASMEM>>>(mask, out);
}

// round 17
// speedup vs baseline: 1.4312x; 1.4312x over previous
#include <cuda_runtime.h>
#include <cuda_fp16.h>
#include <math.h>
#include <stdint.h>

#define BB 2
#define SS 2048
#define HH 16
#define DD 64
#define HID 1024
#define NTOK (BB * SS)
#define LOG2E 1.4426950408889634f
#define QSCALE (0.125f * LOG2E)
#define MASKADD (-64.0f)     // log2-domain; exp2(-64) == 0 in fp16

// -------- scratch (allocation-free __device__ globals) --------
__device__ __half g_x[(size_t)NTOK * HID];               // x, fp16
__device__ __half g_Wkn[(size_t)3 * HID * HID];          // W [k][n], fp16 (no transpose)
__device__ __half g_Qh[(size_t)NTOK * HID];              // [b][h][s][d]
__device__ __half g_Kh[(size_t)NTOK * HID];
__device__ __half g_Vh[(size_t)NTOK * HID];

// ===================== helpers =====================
__device__ __forceinline__ uint32_t smem_u32(const void* p) {
    uint32_t a;
    asm("{ .reg .u64 t; cvta.to.shared.u64 t, %1; cvt.u32.u64 %0, t; }" : "=r"(a) : "l"(p));
    return a;
}
__device__ __forceinline__ uint32_t sw128(uint32_t o) { return o ^ ((o >> 3) & 0x70); }
// swizzle for 256-byte rows: phase = row & 7 (bits 8-10 of offset)
__device__ __forceinline__ uint32_t sw256(uint32_t o) { return o ^ ((o >> 4) & 0x70); }

__device__ __forceinline__ void ldsm4(uint32_t r[4], uint32_t addr) {
    asm volatile("ldmatrix.sync.aligned.m8n8.x4.shared.b16 {%0,%1,%2,%3}, [%4];"
                 : "=r"(r[0]), "=r"(r[1]), "=r"(r[2]), "=r"(r[3]) : "r"(addr));
}
__device__ __forceinline__ void ldsm4t(uint32_t r[4], uint32_t addr) {
    asm volatile("ldmatrix.sync.aligned.m8n8.x4.trans.shared.b16 {%0,%1,%2,%3}, [%4];"
                 : "=r"(r[0]), "=r"(r[1]), "=r"(r[2]), "=r"(r[3]) : "r"(addr));
}
// fp16 MMA, f32 accumulate
__device__ __forceinline__ void mma16816(float c[4], const uint32_t a[4],
                                         uint32_t b0, uint32_t b1) {
    asm volatile(
        "mma.sync.aligned.m16n8k16.row.col.f32.f16.f16.f32 "
        "{%0,%1,%2,%3}, {%4,%5,%6,%7}, {%8,%9}, {%0,%1,%2,%3};"
        : "+f"(c[0]), "+f"(c[1]), "+f"(c[2]), "+f"(c[3])
        : "r"(a[0]), "r"(a[1]), "r"(a[2]), "r"(a[3]), "r"(b0), "r"(b1));
}
// pack RN-fp16 pair: e0 -> low half, e1 -> high half
__device__ __forceinline__ uint32_t packh(float e0, float e1) {
    __half2 h = __floats2half2_rn(e0, e1);
    return *reinterpret_cast<uint32_t*>(&h);
}
// hardware exp2: one MUFU.EX2 (parallel pipe to tensor)
__device__ __forceinline__ float ex2(float x) {
    float y;
    asm("ex2.approx.ftz.f32 %0, %1;" : "=f"(y) : "f"(x));
    return y;
}
__device__ __forceinline__ void cpa16(uint32_t s, const void* g) {
    asm volatile("cp.async.cg.shared.global [%0], [%1], 16;" :: "r"(s), "l"(g));
}
#define CPA_COMMIT() asm volatile("cp.async.commit_group;")
#define CPA_WAIT2()  asm volatile("cp.async.wait_group 2;")
#define CPA_WAIT1()  asm volatile("cp.async.wait_group 1;")
#define CPA_WAIT0()  asm volatile("cp.async.wait_group 0;")

#define ONESF16X2 0x3C003C00u     // half2(1.0, 1.0)

// ===================== prep: pure streaming fp32->fp16 convert =====================
// grid (1024, 1, 7): z<3 -> W slice z (1M floats each), z>=3 -> x quarter z-3.
__global__ void conv_all(const float* __restrict__ x,
                         const float* __restrict__ Wq, const float* __restrict__ Wk,
                         const float* __restrict__ Wv) {
    const int z = blockIdx.z;
    const size_t i = ((size_t)blockIdx.x * 256 + threadIdx.x) * 4;
    if (z < 3) {
        const float* W = (z == 0) ? Wq : (z == 1) ? Wk : Wv;
        float4 v = *(const float4*)(W + i);
        *(uint2*)(g_Wkn + (size_t)z * HID * HID + i) =
            make_uint2(packh(v.x, v.y), packh(v.z, v.w));
    } else {
        size_t off = (size_t)(z - 3) * (HID * HID) + i;
        float4 v = *(const float4*)(x + off);
        *(uint2*)(g_x + off) = make_uint2(packh(v.x, v.y), packh(v.z, v.w));
    }
}

// ===================== QKV GEMM: BM128 x BN128 x BK64, warp tile 32x64 =============
// A tile: 128 m-rows x 128B (sw128). B tile: 64 k-rows x 256B [k][n] (sw256),
// consumed via ldmatrix.trans. ALL LDSMs issued before MMAs per kk (R15 structure).
// stage: A@0(16K) B@16K(16K) = 32K; 3 stages = 96K.
#define GSTAGE 32768
#define GSMEM  (3 * GSTAGE)      // 98304
#define NCHUNK 16

__global__ __launch_bounds__(256, 2)
void qkv_gemm_mma(const float* __restrict__ bq, const float* __restrict__ bk,
                  const float* __restrict__ bv) {
    extern __shared__ __align__(1024) char sm[];
    const int tid = threadIdx.x, lane = tid & 31, wid = tid >> 5;
    const int wm = wid >> 1, wn = wid & 1;     // 4m x 2n warp grid, 32x64 tiles
    const int z = blockIdx.z;
    const int m0 = blockIdx.y * 128;
    const int n0 = blockIdx.x * 128;

    const __half* Wh = g_Wkn + (size_t)z * HID * HID;
    const float* bias = (z == 0) ? bq : (z == 1) ? bk : bv;
    const uint32_t smb = smem_u32(sm);

    auto issue = [&](int c, int s) {
        const uint32_t sb = smb + s * GSTAGE;
        const int k0 = c * 64;
#pragma unroll
        for (int j = 0; j < 4; j++) {               // A: 128 m-rows x 8 x 16B
            int idx = tid + 256 * j;
            int row = idx >> 3, ch = idx & 7;
            uint32_t so = sw128((uint32_t)(row * 128 + ch * 16));
            cpa16(sb + so, g_x + (size_t)(m0 + row) * HID + k0 + ch * 8);
        }
#pragma unroll
        for (int j = 0; j < 4; j++) {               // B: 64 k-rows x 16 x 16B
            int idx = tid + 256 * j;
            int row = idx >> 4, ch = idx & 15;
            uint32_t so = sw256((uint32_t)(row * 256 + ch * 16));
            cpa16(sb + 16384 + so, Wh + (size_t)(k0 + row) * HID + n0 + ch * 8);
        }
        CPA_COMMIT();
    };

    float acc[2][8][4];
#pragma unroll
    for (int i = 0; i < 2; i++)
#pragma unroll
        for (int j = 0; j < 8; j++)
#pragma unroll
            for (int v = 0; v < 4; v++) acc[i][j][v] = 0.f;

    issue(0, 0); issue(1, 1); issue(2, 2);

    uint32_t offA[4], offB[4];
    {
        const int rA = wm * 32 + (lane & 15);
#pragma unroll
        for (int kk = 0; kk < 4; kk++) {
            const int cA = kk * 32 + (lane >> 4) * 16;
            offA[kk] = sw128((uint32_t)(rA * 128 + cA));
        }
        // B: rows = k (lane&15), col bytes = wn*128 + dg*32 + (lane>>4)*16
        const int rB = lane & 15;
#pragma unroll
        for (int dg = 0; dg < 4; dg++) {
            const int cB = wn * 128 + dg * 32 + (lane >> 4) * 16;
            offB[dg] = 16384 + sw256((uint32_t)(rB * 256 + cB));
        }
    }

    for (int c = 0; c < NCHUNK; c++) {
        const int s = c % 3;
        const uint32_t sb = smb + s * GSTAGE;
        if (c <= NCHUNK - 3) CPA_WAIT2();
        else if (c == NCHUNK - 2) CPA_WAIT1();
        else CPA_WAIT0();
        __syncthreads();

#pragma unroll
        for (int kk = 0; kk < 4; kk++) {
            // issue ALL loads first (R15 structure), then all MMAs
            const uint32_t aA = sb + offA[kk];
            const uint32_t kb = kk * 4096;      // 16 k-rows x 256B
            uint32_t ah[2][4], bt[4][4];
            ldsm4(ah[0], aA);           ldsm4(ah[1], aA + 2048);
            ldsm4t(bt[0], sb + offB[0] + kb);
            ldsm4t(bt[1], sb + offB[1] + kb);
            ldsm4t(bt[2], sb + offB[2] + kb);
            ldsm4t(bt[3], sb + offB[3] + kb);
#pragma unroll
            for (int dg = 0; dg < 4; dg++) {
#pragma unroll
                for (int mi = 0; mi < 2; mi++) {
                    mma16816(acc[mi][2 * dg],     ah[mi], bt[dg][0], bt[dg][1]);
                    mma16816(acc[mi][2 * dg + 1], ah[mi], bt[dg][2], bt[dg][3]);
                }
            }
        }
        __syncthreads();
        if (c + 3 < NCHUNK) issue(c + 3, (c + 3) % 3);
    }

    __half* outh = (z == 0) ? g_Qh : (z == 1) ? g_Kh : g_Vh;
    const float sc = (z == 0) ? QSCALE : 1.0f;
#pragma unroll
    for (int mi = 0; mi < 2; mi++) {
        int r0 = m0 + wm * 32 + mi * 16 + (lane >> 2);
#pragma unroll
        for (int nj = 0; nj < 8; nj++) {
            int col = n0 + wn * 64 + nj * 8 + 2 * (lane & 3);
            float b0v = __ldg(&bias[col]), b1v = __ldg(&bias[col + 1]);
#pragma unroll
            for (int half_ = 0; half_ < 2; half_++) {
                int r = r0 + half_ * 8;
                float v0 = (acc[mi][nj][half_ * 2 + 0] + b0v) * sc;
                float v1 = (acc[mi][nj][half_ * 2 + 1] + b1v) * sc;
                size_t off = (((size_t)((r >> 11) * HH + (col >> 6)) * SS +
                               (r & (SS - 1))) * DD) + (col & (DD - 1));
                *(uint32_t*)(outh + off) = packh(v0, v1);
            }
        }
    }
}

// ===================== flash attention (unchanged from R14) =====================
#define ASTAGE 32768
#define AADDER (3 * ASTAGE)              // 98304
#define AFLAGS (AADDER + SS * 4)         // 106496
#define ASMEM  (AFLAGS + 128)            // 106624
#define NPAIR 16

__global__ __launch_bounds__(256, 2)
void attn_mma(const int* __restrict__ mask, float* __restrict__ out) {
    extern __shared__ __align__(1024) char sm[];
    const int tid = threadIdx.x, lane = tid & 31, wid = tid >> 5;
    const int q0 = blockIdx.x * 128;
    const int h = blockIdx.y, b = blockIdx.z;
    const size_t hb = (size_t)(b * HH + h) * SS * DD;
    const uint32_t smb = smem_u32(sm);

    // ---- prologue: stage Q, mask adders ----
#pragma unroll
    for (int j = 0; j < 4; j++) {
        int idx = tid + 256 * j;
        int row = idx >> 3, ch = idx & 7;
        uint32_t so = sw128((uint32_t)(row * 128 + ch * 16));
        *(uint4*)(sm + so) = *(const uint4*)(g_Qh + hb + (size_t)(q0 + row) * DD + ch * 8);
    }
#pragma unroll
    for (int j = 0; j < SS / 256; j++) {
        int i = tid + 256 * j;
        ((float*)(sm + AADDER))[i] = mask[b * SS + i] ? 0.f : MASKADD;
    }
    __syncthreads();
    uint32_t qh[4][4];
    {
        int r = wid * 16 + (lane & 15);
#pragma unroll
        for (int kk = 0; kk < 4; kk++) {
            int cB = kk * 32 + (lane >> 4) * 16;
            ldsm4(qh[kk], smb + sw128((uint32_t)(r * 128 + cB)));
        }
    }
    // per-64-key-block "fully unmasked" flags
    if (tid < 32) {
        const float* ad = (const float*)(sm + AADDER) + tid * 64;
        int ok = 1;
#pragma unroll 8
        for (int i = 0; i < 64; i++) ok &= (ad[i] == 0.0f);
        ((int*)(sm + AFLAGS))[tid] = ok;
    }
    __syncthreads();

    auto issue = [&](int p, int s) {       // loads 128 keys (pair p) into stage s
        const uint32_t sb = smb + s * ASTAGE;
        const int c0 = p * 128;
#pragma unroll
        for (int j = 0; j < 4; j++) {
            int idx = tid + 256 * j;
            int row = idx >> 3, ch = idx & 7;
            uint32_t so = sw128((uint32_t)(row * 128 + ch * 16));
            size_t g = hb + (size_t)(c0 + row) * DD + ch * 8;
            cpa16(sb + so,         g_Kh + g);
            cpa16(sb + 16384 + so, g_Vh + g);
        }
        CPA_COMMIT();
    };

    float ctx[8][4];
#pragma unroll
    for (int i = 0; i < 8; i++)
#pragma unroll
        for (int j = 0; j < 4; j++) ctx[i][j] = 0.f;
    float lacc[4] = {0.f, 0.f, 0.f, 0.f};

    issue(0, 0); issue(1, 1); issue(2, 2);

    uint32_t off4[4];
    {
        const int rk = lane & 15;
#pragma unroll
        for (int i = 0; i < 4; i++) {
            const int cB = i * 32 + (lane >> 4) * 16;
            off4[i] = sw128((uint32_t)(rk * 128 + cB));
        }
    }
    const int kcol = 2 * (lane & 3);
    const int* flags = (const int*)(sm + AFLAGS);

    for (int p = 0; p < NPAIR; p++) {
        const int s = p % 3;
        const uint32_t sb = smb + s * ASTAGE;
        if (p <= NPAIR - 3) CPA_WAIT2();
        else if (p == NPAIR - 2) CPA_WAIT1();
        else CPA_WAIT0();
        __syncthreads();

#pragma unroll
        for (int hf = 0; hf < 2; hf++) {
            const int c = 2 * p + hf;
            const uint32_t koff = hf * 8192;

            float sacc[8][4];
#pragma unroll
            for (int i = 0; i < 8; i++)
#pragma unroll
                for (int j = 0; j < 4; j++) sacc[i][j] = 0.f;

#pragma unroll
            for (int kk = 0; kk < 4; kk++) {
                const uint32_t ka = sb + koff + off4[kk];
#pragma unroll
                for (int g = 0; g < 4; g++) {
                    uint32_t kh[4];
                    ldsm4(kh, ka + g * 2048);
                    mma16816(sacc[2 * g],     qh[kk], kh[0], kh[2]);
                    mma16816(sacc[2 * g + 1], qh[kk], kh[1], kh[3]);
                }
            }

            uint32_t ph[4][4];
            if (flags[c]) {
#pragma unroll
                for (int kg = 0; kg < 4; kg++) {
                    const float* s0 = sacc[2 * kg];
                    const float* s1 = sacc[2 * kg + 1];
                    ph[kg][0] = packh(ex2(s0[0]), ex2(s0[1]));
                    ph[kg][1] = packh(ex2(s0[2]), ex2(s0[3]));
                    ph[kg][2] = packh(ex2(s1[0]), ex2(s1[1]));
                    ph[kg][3] = packh(ex2(s1[2]), ex2(s1[3]));
                }
            } else {
                const float* madd = (const float*)(sm + AADDER) + c * 64;
#pragma unroll
                for (int kg = 0; kg < 4; kg++) {
                    const float* s0 = sacc[2 * kg];
                    const float* s1 = sacc[2 * kg + 1];
                    float a0 = madd[kg * 16 + kcol];
                    float a1 = madd[kg * 16 + kcol + 1];
                    float a2 = madd[kg * 16 + 8 + kcol];
                    float a3 = madd[kg * 16 + 8 + kcol + 1];
                    ph[kg][0] = packh(ex2(s0[0] + a0), ex2(s0[1] + a1));
                    ph[kg][1] = packh(ex2(s0[2] + a0), ex2(s0[3] + a1));
                    ph[kg][2] = packh(ex2(s1[0] + a2), ex2(s1[1] + a3));
                    ph[kg][3] = packh(ex2(s1[2] + a2), ex2(s1[3] + a3));
                }
            }

#pragma unroll
            for (int kg = 0; kg < 4; kg++)
                mma16816(lacc, ph[kg], ONESF16X2, ONESF16X2);

#pragma unroll
            for (int dg = 0; dg < 4; dg++) {
                const uint32_t va = sb + 16384 + koff + off4[dg];
#pragma unroll
                for (int kg = 0; kg < 4; kg++) {
                    uint32_t vh[4];
                    ldsm4t(vh, va + kg * 2048);
                    mma16816(ctx[2 * dg],     ph[kg], vh[0], vh[1]);
                    mma16816(ctx[2 * dg + 1], ph[kg], vh[2], vh[3]);
                }
            }
        }
        __syncthreads();
        if (p + 3 < NPAIR) issue(p + 3, (p + 3) % 3);
    }

    const float inv0 = 1.0f / lacc[0], inv1 = 1.0f / lacc[2];
    const int r0 = q0 + wid * 16 + (lane >> 2);
    const int dbase = 2 * (lane & 3);
#pragma unroll
    for (int nj = 0; nj < 8; nj++) {
        int d = nj * 8 + dbase;
        float2 v0 = make_float2(ctx[nj][0] * inv0, ctx[nj][1] * inv0);
        float2 v1 = make_float2(ctx[nj][2] * inv1, ctx[nj][3] * inv1);
        *(float2*)&out[(size_t)(b * SS + r0) * HID + h * DD + d] = v0;
        *(float2*)&out[(size_t)(b * SS + r0 + 8) * HID + h * DD + d] = v1;
    }
}

// ===================== launch =====================
extern "C" void kernel_launch(void* const* d_in, const int* in_sizes, int n_in,
                              void* d_out, int out_size) {
    const float* x    = (const float*)d_in[0];
    const int*   mask = (const int*)d_in[1];
    const float* Wq   = (const float*)d_in[2];
    const float* bq   = (const float*)d_in[3];
    const float* Wk   = (const float*)d_in[4];
    const float* bk   = (const float*)d_in[5];
    const float* Wv   = (const float*)d_in[6];
    const float* bv   = (const float*)d_in[7];
    float* out = (float*)d_out;

    static int attr_done = 0;
    if (!attr_done) {
        cudaFuncSetAttribute(qkv_gemm_mma,
                             cudaFuncAttributeMaxDynamicSharedMemorySize, GSMEM);
        cudaFuncSetAttribute(attn_mma,
                             cudaFuncAttributeMaxDynamicSharedMemorySize, ASMEM);
        attr_done = 1;
    }

    dim3 pgrid(1024, 1, 7);
    conv_all<<<pgrid, 256>>>(x, Wq, Wk, Wv);

    dim3 ggrid(HID / 128, NTOK / 128, 3);
    qkv_gemm_mma<<<ggrid, 256, GSMEM>>>(bq, bk, bv);

    dim3 agrid(SS / 128, HH, BB);
    attn_mma<<<agrid, 256, ASMEM>>>(mask, out);
}